// round 4
// baseline (speedup 1.0000x reference)
#include <cuda_runtime.h>
#include <cuda_bf16.h>
#include <cuda_fp16.h>
#include <cstddef>

#define MAXN 50000
#define MAXE 800000

// ---------------- scratch (device globals; no allocs allowed) ----------------
__device__ int   g_deg[MAXN];
__device__ int   g_rowptr[MAXN + 1];
__device__ int   g_fill[MAXN];
__device__ int   g_col[MAXE];

__device__ float g_h1[(size_t)MAXN * 256];     // layer1 linear out (fp32)
__device__ uint2 g_h1h[(size_t)MAXN * 64];     // fp16 shadow of h1 (4 halves per uint2)
__device__ float g_hrelu[(size_t)MAXN * 256];  // layer1 GAT out (post relu)
__device__ float g_h2[(size_t)MAXN * 64];      // layer2 linear out
__device__ float g_as1[MAXN * 4], g_ad1[MAXN * 4];
__device__ float g_as2[MAXN],     g_ad2[MAXN];

// ---------------- CSR build ----------------
__global__ void k_zero_deg(int N) {
    int i = blockIdx.x * blockDim.x + threadIdx.x;
    if (i < N) g_deg[i] = 0;
}

__global__ void k_hist(const int* __restrict__ dst, int E, int N) {
    int i = blockIdx.x * blockDim.x + threadIdx.x;
    if (i < E) {
        int d = dst[i];
        if (d >= 0 && d < N) atomicAdd(&g_deg[d], 1);
    }
}

__global__ void k_scan(int N) {
    __shared__ int sh[1024];
    int t = threadIdx.x;
    int carry = 0;
    for (int base = 0; base < N; base += 1024) {
        int i = base + t;
        int v = (i < N) ? g_deg[i] : 0;
        sh[t] = v;
        __syncthreads();
        #pragma unroll
        for (int off = 1; off < 1024; off <<= 1) {
            int x = (t >= off) ? sh[t - off] : 0;
            __syncthreads();
            sh[t] += x;
            __syncthreads();
        }
        int excl = carry + sh[t] - v;
        if (i < N) { g_rowptr[i] = excl; g_fill[i] = excl; }
        carry += sh[1023];
        __syncthreads();
    }
    if (t == 0) g_rowptr[N] = carry;
}

__global__ void k_scatter(const int* __restrict__ src,
                          const int* __restrict__ dst, int E, int N) {
    int i = blockIdx.x * blockDim.x + threadIdx.x;
    if (i < E) {
        int d = dst[i];
        if (d >= 0 && d < N) {
            int pos = atomicAdd(&g_fill[d], 1);
            g_col[pos] = src[i];
        }
    }
}

// ---------------- SGEMM: C[M,N] = A[M,K] @ B[K,N], row-major fp32 ----------------
// 128x64 tile, BK=16, 256 threads, 8x4 microtile, double-buffered smem.
__global__ void __launch_bounds__(256, 2)
k_sgemm(const float* __restrict__ A, const float* __restrict__ B,
        float* __restrict__ C, int M, int N, int K) {
    __shared__ float As[2][16][132];
    __shared__ float Bs[2][16][64];

    int tid = threadIdx.x;
    int row0 = blockIdx.y * 128, col0 = blockIdx.x * 64;

    int aRow = tid >> 2, aK = (tid & 3) * 4;
    int bRow = tid >> 4, bCol = (tid & 15) * 4;
    int ty = tid >> 4;
    int tx = tid & 15;

    float acc[8][4];
    #pragma unroll
    for (int i = 0; i < 8; i++)
        #pragma unroll
        for (int j = 0; j < 4; j++) acc[i][j] = 0.f;

    int nk = K >> 4;
    float4 aReg[2], bReg;

    #pragma unroll
    for (int p = 0; p < 2; p++) {
        int r = row0 + aRow + p * 64;
        aReg[p] = (r < M) ? *(const float4*)(A + (size_t)r * K + aK)
                          : make_float4(0.f, 0.f, 0.f, 0.f);
    }
    bReg = *(const float4*)(B + (size_t)bRow * N + col0 + bCol);
    #pragma unroll
    for (int p = 0; p < 2; p++) {
        int r = aRow + p * 64;
        As[0][aK + 0][r] = aReg[p].x; As[0][aK + 1][r] = aReg[p].y;
        As[0][aK + 2][r] = aReg[p].z; As[0][aK + 3][r] = aReg[p].w;
    }
    *(float4*)(&Bs[0][bRow][bCol]) = bReg;
    __syncthreads();

    for (int t = 0; t < nk; t++) {
        int buf = t & 1;
        int nxt = t + 1;
        if (nxt < nk) {
            int k0 = nxt << 4;
            #pragma unroll
            for (int p = 0; p < 2; p++) {
                int r = row0 + aRow + p * 64;
                aReg[p] = (r < M) ? *(const float4*)(A + (size_t)r * K + k0 + aK)
                                  : make_float4(0.f, 0.f, 0.f, 0.f);
            }
            bReg = *(const float4*)(B + (size_t)(k0 + bRow) * N + col0 + bCol);
        }
        #pragma unroll
        for (int k = 0; k < 16; k++) {
            float4 a0 = *(const float4*)&As[buf][k][ty * 8];
            float4 a1 = *(const float4*)&As[buf][k][ty * 8 + 4];
            float4 b4 = *(const float4*)&Bs[buf][k][tx * 4];
            float a[8] = {a0.x, a0.y, a0.z, a0.w, a1.x, a1.y, a1.z, a1.w};
            float b[4] = {b4.x, b4.y, b4.z, b4.w};
            #pragma unroll
            for (int i = 0; i < 8; i++)
                #pragma unroll
                for (int j = 0; j < 4; j++) acc[i][j] += a[i] * b[j];
        }
        if (nxt < nk) {
            int nb = nxt & 1;
            #pragma unroll
            for (int p = 0; p < 2; p++) {
                int r = aRow + p * 64;
                As[nb][aK + 0][r] = aReg[p].x; As[nb][aK + 1][r] = aReg[p].y;
                As[nb][aK + 2][r] = aReg[p].z; As[nb][aK + 3][r] = aReg[p].w;
            }
            *(float4*)(&Bs[nb][bRow][bCol]) = bReg;
            __syncthreads();
        }
    }

    #pragma unroll
    for (int i = 0; i < 8; i++) {
        int row = row0 + ty * 8 + i;
        if (row < M) {
            float4 o = make_float4(acc[i][0], acc[i][1], acc[i][2], acc[i][3]);
            *(float4*)(C + (size_t)row * N + col0 + tx * 4) = o;
        }
    }
}

// ---------------- attention coefficients (+ fp16 shadow write for layer1) ----------------
__global__ void k_alpha1(const float* __restrict__ aw_s, const float* __restrict__ aw_d, int N) {
    int gt = blockIdx.x * blockDim.x + threadIdx.x;
    int n = gt >> 5, lane = gt & 31;
    if (n >= N) return;
    const float* hrow = g_h1 + (size_t)n * 256;
    __half* hh = (__half*)(g_h1h + (size_t)n * 64);
    float ps[4] = {0.f, 0.f, 0.f, 0.f}, pd[4] = {0.f, 0.f, 0.f, 0.f};
    #pragma unroll
    for (int r = 0; r < 8; r++) {
        float v = hrow[r * 32 + lane];
        hh[r * 32 + lane] = __float2half(v);          // fp16 shadow for the gather
        int h = r >> 1;
        int cc = (r & 1) * 32 + lane;
        ps[h] += v * aw_s[h * 64 + cc];
        pd[h] += v * aw_d[h * 64 + cc];
    }
    #pragma unroll
    for (int h = 0; h < 4; h++) {
        float s = ps[h], d = pd[h];
        #pragma unroll
        for (int off = 16; off; off >>= 1) {
            s += __shfl_xor_sync(0xffffffffu, s, off);
            d += __shfl_xor_sync(0xffffffffu, d, off);
        }
        if (lane == 0) { g_as1[n * 4 + h] = s; g_ad1[n * 4 + h] = d; }
    }
}

__global__ void k_alpha2(const float* __restrict__ aw_s, const float* __restrict__ aw_d, int N) {
    int gt = blockIdx.x * blockDim.x + threadIdx.x;
    int n = gt >> 5, lane = gt & 31;
    if (n >= N) return;
    const float* hrow = g_h2 + (size_t)n * 64;
    float v0 = hrow[lane], v1 = hrow[lane + 32];
    float s = v0 * aw_s[lane] + v1 * aw_s[lane + 32];
    float d = v0 * aw_d[lane] + v1 * aw_d[lane + 32];
    #pragma unroll
    for (int off = 16; off; off >>= 1) {
        s += __shfl_xor_sync(0xffffffffu, s, off);
        d += __shfl_xor_sync(0xffffffffu, d, off);
    }
    if (lane == 0) { g_as2[n] = s; g_ad2[n] = d; }
}

// ---------------- aggregation (warp per dst node, CSR gather, no atomics) ----------------
// layer1: fp16 gather (halved traffic). lane covers 4 halves at c=lane*4 (head lane>>4)
// and 4 halves at c=128+lane*4 (head 2+lane>>4).
__global__ void k_agg1(const float* __restrict__ b1, int N) {
    int gt = blockIdx.x * blockDim.x + threadIdx.x;
    int n = gt >> 5, lane = gt & 31;
    if (n >= N) return;
    int h0 = lane >> 4, h1 = h0 + 2;
    float ad0 = g_ad1[n * 4 + h0];
    float ad1v = g_ad1[n * 4 + h1];
    const uint2* H = g_h1h;
    float4 acc0 = make_float4(0.f, 0.f, 0.f, 0.f), acc1 = acc0;
    float s0 = 0.f, s1 = 0.f;

    int beg = g_rowptr[n], end = g_rowptr[n + 1];
    int srcCur = n;                                   // self loop first
    int e = beg;
    for (;;) {
        int srcNext = (e < end) ? g_col[e] : -1;      // prefetched while processing srcCur
        float t0 = g_as1[srcCur * 4 + h0] + ad0;  t0 = (t0 > 0.f) ? t0 : 0.2f * t0;
        float t1 = g_as1[srcCur * 4 + h1] + ad1v; t1 = (t1 > 0.f) ? t1 : 0.2f * t1;
        float x0 = __expf(t0), x1 = __expf(t1);
        uint2 p0 = H[(size_t)srcCur * 64 + lane];
        uint2 p1 = H[(size_t)srcCur * 64 + 32 + lane];
        float2 a = __half22float2(*(const __half2*)&p0.x);
        float2 bq = __half22float2(*(const __half2*)&p0.y);
        float2 c = __half22float2(*(const __half2*)&p1.x);
        float2 d = __half22float2(*(const __half2*)&p1.y);
        acc0.x += x0 * a.x;  acc0.y += x0 * a.y;  acc0.z += x0 * bq.x; acc0.w += x0 * bq.y;
        acc1.x += x1 * c.x;  acc1.y += x1 * c.y;  acc1.z += x1 * d.x;  acc1.w += x1 * d.y;
        s0 += x0; s1 += x1;
        if (srcNext < 0) break;
        srcCur = srcNext; e++;
    }
    float i0 = 1.f / s0, i1 = 1.f / s1;
    int c0 = lane * 4, c1 = 128 + lane * 4;
    float4 o0, o1;
    o0.x = fmaxf(acc0.x * i0 + b1[c0 + 0], 0.f);
    o0.y = fmaxf(acc0.y * i0 + b1[c0 + 1], 0.f);
    o0.z = fmaxf(acc0.z * i0 + b1[c0 + 2], 0.f);
    o0.w = fmaxf(acc0.w * i0 + b1[c0 + 3], 0.f);
    o1.x = fmaxf(acc1.x * i1 + b1[c1 + 0], 0.f);
    o1.y = fmaxf(acc1.y * i1 + b1[c1 + 1], 0.f);
    o1.z = fmaxf(acc1.z * i1 + b1[c1 + 2], 0.f);
    o1.w = fmaxf(acc1.w * i1 + b1[c1 + 3], 0.f);
    float4* O = (float4*)g_hrelu;
    O[(size_t)n * 64 + lane] = o0;
    O[(size_t)n * 64 + 32 + lane] = o1;
}

// layer2: fp32 gather (keeps error budget; only ~25us).
__global__ void k_agg2(const float* __restrict__ b2, float* __restrict__ out, int N) {
    int gt = blockIdx.x * blockDim.x + threadIdx.x;
    int n = gt >> 5, lane = gt & 31;
    if (n >= N) return;
    float ad = g_ad2[n];
    const float2* H = (const float2*)g_h2;
    float2 acc = make_float2(0.f, 0.f);
    float s = 0.f;
    int beg = g_rowptr[n], end = g_rowptr[n + 1];
    int srcCur = n;
    int e = beg;
    for (;;) {
        int srcNext = (e < end) ? g_col[e] : -1;
        float t = g_as2[srcCur] + ad; t = (t > 0.f) ? t : 0.2f * t;
        float x = __expf(t);
        float2 v = H[(size_t)srcCur * 32 + lane];
        acc.x += x * v.x; acc.y += x * v.y;
        s += x;
        if (srcNext < 0) break;
        srcCur = srcNext; e++;
    }
    float inv = 1.f / s;
    float2 o;
    o.x = acc.x * inv + b2[lane * 2 + 0];
    o.y = acc.y * inv + b2[lane * 2 + 1];
    ((float2*)out)[(size_t)n * 32 + lane] = o;
}

// ---------------- launch ----------------
extern "C" void kernel_launch(void* const* d_in, const int* in_sizes, int n_in,
                              void* d_out, int out_size) {
    const float* x    = (const float*)d_in[0];
    const int*   ei   = (const int*)d_in[1];
    const float* W1   = (const float*)d_in[2];
    const float* as1w = (const float*)d_in[3];
    const float* ad1w = (const float*)d_in[4];
    const float* b1   = (const float*)d_in[5];
    const float* W2   = (const float*)d_in[6];
    const float* as2w = (const float*)d_in[7];
    const float* ad2w = (const float*)d_in[8];
    const float* b2   = (const float*)d_in[9];

    int N = in_sizes[0] / 128;
    int E = in_sizes[1] / 2;
    const int* srcp = ei;
    const int* dstp = ei + E;

    void *p_h1, *p_hrelu, *p_h2;
    cudaGetSymbolAddress(&p_h1, g_h1);
    cudaGetSymbolAddress(&p_hrelu, g_hrelu);
    cudaGetSymbolAddress(&p_h2, g_h2);

    static cudaStream_t s2 = nullptr;
    static cudaEvent_t ev_fork = nullptr, ev_join = nullptr;
    if (!s2) {
        cudaStreamCreateWithFlags(&s2, cudaStreamNonBlocking);
        cudaEventCreateWithFlags(&ev_fork, cudaEventDisableTiming);
        cudaEventCreateWithFlags(&ev_join, cudaEventDisableTiming);
    }

    // fork: CSR build runs concurrently with layer-1 GEMM
    cudaEventRecord(ev_fork, 0);
    cudaStreamWaitEvent(s2, ev_fork, 0);
    k_zero_deg<<<(N + 255) / 256, 256, 0, s2>>>(N);
    k_hist<<<(E + 255) / 256, 256, 0, s2>>>(dstp, E, N);
    k_scan<<<1, 1024, 0, s2>>>(N);
    k_scatter<<<(E + 255) / 256, 256, 0, s2>>>(srcp, dstp, E, N);
    cudaEventRecord(ev_join, s2);

    // layer 1 linear + attention coefficients (independent of CSR)
    dim3 g1(256 / 64, (N + 127) / 128);
    k_sgemm<<<g1, 256>>>(x, W1, (float*)p_h1, N, 256, 128);
    k_alpha1<<<(N * 32 + 255) / 256, 256>>>(as1w, ad1w, N);

    // join, then aggregation + layer 2
    cudaStreamWaitEvent(0, ev_join, 0);
    k_agg1<<<(N * 32 + 255) / 256, 256>>>(b1, N);

    dim3 g2(64 / 64, (N + 127) / 128);
    k_sgemm<<<g2, 256>>>((const float*)p_hrelu, W2, (float*)p_h2, N, 64, 256);
    k_alpha2<<<(N * 32 + 255) / 256, 256>>>(as2w, ad2w, N);
    k_agg2<<<(N * 32 + 255) / 256, 256>>>(b2, (float*)d_out, N);
}

// round 9
// speedup vs baseline: 1.5620x; 1.5620x over previous
#include <cuda_runtime.h>
#include <cuda_bf16.h>
#include <cuda_fp16.h>
#include <cstddef>

#define MAXN 50000
#define MAXE 800000

// ---------------- scratch (device globals; no allocs allowed) ----------------
__device__ int   g_deg[MAXN];
__device__ int   g_rowptr[MAXN + 1];
__device__ int   g_fill[MAXN];
__device__ int   g_col[MAXE];

__device__ float g_h1[(size_t)MAXN * 256];     // layer1 linear out (fp32)
__device__ uint2 g_h1h[(size_t)MAXN * 64];     // fp16 shadow of h1 (4 halves per uint2)
__device__ float g_hrelu[(size_t)MAXN * 256];  // layer1 GAT out (post relu)
__device__ float g_h2[(size_t)MAXN * 64];      // layer2 linear out
__device__ float g_as1[MAXN * 4], g_ad1[MAXN * 4];
__device__ float g_as2[MAXN],     g_ad2[MAXN];

// ---------------- CSR build ----------------
__global__ void k_zero_deg(int N) {
    int i = blockIdx.x * blockDim.x + threadIdx.x;
    if (i < N) g_deg[i] = 0;
}

__global__ void k_hist(const int* __restrict__ dst, int E, int N) {
    int i = blockIdx.x * blockDim.x + threadIdx.x;
    if (i < E) {
        int d = dst[i];
        if (d >= 0 && d < N) atomicAdd(&g_deg[d], 1);
    }
}

__global__ void k_scan(int N) {
    __shared__ int sh[1024];
    int t = threadIdx.x;
    int carry = 0;
    for (int base = 0; base < N; base += 1024) {
        int i = base + t;
        int v = (i < N) ? g_deg[i] : 0;
        sh[t] = v;
        __syncthreads();
        #pragma unroll
        for (int off = 1; off < 1024; off <<= 1) {
            int x = (t >= off) ? sh[t - off] : 0;
            __syncthreads();
            sh[t] += x;
            __syncthreads();
        }
        int excl = carry + sh[t] - v;
        if (i < N) { g_rowptr[i] = excl; g_fill[i] = excl; }
        carry += sh[1023];
        __syncthreads();
    }
    if (t == 0) g_rowptr[N] = carry;
}

__global__ void k_scatter(const int* __restrict__ src,
                          const int* __restrict__ dst, int E, int N) {
    int i = blockIdx.x * blockDim.x + threadIdx.x;
    if (i < E) {
        int d = dst[i];
        if (d >= 0 && d < N) {
            int pos = atomicAdd(&g_fill[d], 1);
            g_col[pos] = src[i];
        }
    }
}

// ---------------- SGEMM: C[M,N] = A[M,K] @ B[K,N], row-major fp32 ----------------
// 128x64 tile, BK=16, 256 threads, 8x4 microtile, double-buffered smem.
__global__ void __launch_bounds__(256, 2)
k_sgemm(const float* __restrict__ A, const float* __restrict__ B,
        float* __restrict__ C, int M, int N, int K) {
    __shared__ float As[2][16][132];
    __shared__ float Bs[2][16][64];

    int tid = threadIdx.x;
    int row0 = blockIdx.y * 128, col0 = blockIdx.x * 64;

    int aRow = tid >> 2, aK = (tid & 3) * 4;
    int bRow = tid >> 4, bCol = (tid & 15) * 4;
    int ty = tid >> 4;
    int tx = tid & 15;

    float acc[8][4];
    #pragma unroll
    for (int i = 0; i < 8; i++)
        #pragma unroll
        for (int j = 0; j < 4; j++) acc[i][j] = 0.f;

    int nk = K >> 4;
    float4 aReg[2], bReg;

    #pragma unroll
    for (int p = 0; p < 2; p++) {
        int r = row0 + aRow + p * 64;
        aReg[p] = (r < M) ? *(const float4*)(A + (size_t)r * K + aK)
                          : make_float4(0.f, 0.f, 0.f, 0.f);
    }
    bReg = *(const float4*)(B + (size_t)bRow * N + col0 + bCol);
    #pragma unroll
    for (int p = 0; p < 2; p++) {
        int r = aRow + p * 64;
        As[0][aK + 0][r] = aReg[p].x; As[0][aK + 1][r] = aReg[p].y;
        As[0][aK + 2][r] = aReg[p].z; As[0][aK + 3][r] = aReg[p].w;
    }
    *(float4*)(&Bs[0][bRow][bCol]) = bReg;
    __syncthreads();

    for (int t = 0; t < nk; t++) {
        int buf = t & 1;
        int nxt = t + 1;
        if (nxt < nk) {
            int k0 = nxt << 4;
            #pragma unroll
            for (int p = 0; p < 2; p++) {
                int r = row0 + aRow + p * 64;
                aReg[p] = (r < M) ? *(const float4*)(A + (size_t)r * K + k0 + aK)
                                  : make_float4(0.f, 0.f, 0.f, 0.f);
            }
            bReg = *(const float4*)(B + (size_t)(k0 + bRow) * N + col0 + bCol);
        }
        #pragma unroll
        for (int k = 0; k < 16; k++) {
            float4 a0 = *(const float4*)&As[buf][k][ty * 8];
            float4 a1 = *(const float4*)&As[buf][k][ty * 8 + 4];
            float4 b4 = *(const float4*)&Bs[buf][k][tx * 4];
            float a[8] = {a0.x, a0.y, a0.z, a0.w, a1.x, a1.y, a1.z, a1.w};
            float b[4] = {b4.x, b4.y, b4.z, b4.w};
            #pragma unroll
            for (int i = 0; i < 8; i++)
                #pragma unroll
                for (int j = 0; j < 4; j++) acc[i][j] += a[i] * b[j];
        }
        if (nxt < nk) {
            int nb = nxt & 1;
            #pragma unroll
            for (int p = 0; p < 2; p++) {
                int r = aRow + p * 64;
                As[nb][aK + 0][r] = aReg[p].x; As[nb][aK + 1][r] = aReg[p].y;
                As[nb][aK + 2][r] = aReg[p].z; As[nb][aK + 3][r] = aReg[p].w;
            }
            *(float4*)(&Bs[nb][bRow][bCol]) = bReg;
            __syncthreads();
        }
    }

    #pragma unroll
    for (int i = 0; i < 8; i++) {
        int row = row0 + ty * 8 + i;
        if (row < M) {
            float4 o = make_float4(acc[i][0], acc[i][1], acc[i][2], acc[i][3]);
            *(float4*)(C + (size_t)row * N + col0 + tx * 4) = o;
        }
    }
}

// ---------------- attention coefficients (+ fp16 shadow write for layer1) ----------------
__global__ void k_alpha1(const float* __restrict__ aw_s, const float* __restrict__ aw_d, int N) {
    int gt = blockIdx.x * blockDim.x + threadIdx.x;
    int n = gt >> 5, lane = gt & 31;
    if (n >= N) return;
    const float* hrow = g_h1 + (size_t)n * 256;
    __half* hh = (__half*)(g_h1h + (size_t)n * 64);
    float ps[4] = {0.f, 0.f, 0.f, 0.f}, pd[4] = {0.f, 0.f, 0.f, 0.f};
    #pragma unroll
    for (int r = 0; r < 8; r++) {
        float v = hrow[r * 32 + lane];
        hh[r * 32 + lane] = __float2half(v);          // fp16 shadow for the gather
        int h = r >> 1;
        int cc = (r & 1) * 32 + lane;
        ps[h] += v * aw_s[h * 64 + cc];
        pd[h] += v * aw_d[h * 64 + cc];
    }
    #pragma unroll
    for (int h = 0; h < 4; h++) {
        float s = ps[h], d = pd[h];
        #pragma unroll
        for (int off = 16; off; off >>= 1) {
            s += __shfl_xor_sync(0xffffffffu, s, off);
            d += __shfl_xor_sync(0xffffffffu, d, off);
        }
        if (lane == 0) { g_as1[n * 4 + h] = s; g_ad1[n * 4 + h] = d; }
    }
}

__global__ void k_alpha2(const float* __restrict__ aw_s, const float* __restrict__ aw_d, int N) {
    int gt = blockIdx.x * blockDim.x + threadIdx.x;
    int n = gt >> 5, lane = gt & 31;
    if (n >= N) return;
    const float* hrow = g_h2 + (size_t)n * 64;
    float v0 = hrow[lane], v1 = hrow[lane + 32];
    float s = v0 * aw_s[lane] + v1 * aw_s[lane + 32];
    float d = v0 * aw_d[lane] + v1 * aw_d[lane + 32];
    #pragma unroll
    for (int off = 16; off; off >>= 1) {
        s += __shfl_xor_sync(0xffffffffu, s, off);
        d += __shfl_xor_sync(0xffffffffu, d, off);
    }
    if (lane == 0) { g_as2[n] = s; g_ad2[n] = d; }
}

// ---------------- aggregation (warp per dst node, CSR gather, no atomics) ----------------
// COUNTED loop (compiler-pipelinable; no data-dependent exit). layer1 gathers fp16.
__global__ void k_agg1(const float* __restrict__ b1, int N) {
    int gt = blockIdx.x * blockDim.x + threadIdx.x;
    int n = gt >> 5, lane = gt & 31;
    if (n >= N) return;
    int h0 = lane >> 4, h1 = h0 + 2;
    float ad0 = g_ad1[n * 4 + h0];
    float ad1v = g_ad1[n * 4 + h1];
    const uint2* H = g_h1h;
    float4 acc0 = make_float4(0.f, 0.f, 0.f, 0.f), acc1 = acc0;
    float s0 = 0.f, s1 = 0.f;
    int beg = g_rowptr[n], end = g_rowptr[n + 1];
    for (int e = beg - 1; e < end; e++) {            // e == beg-1 -> self loop
        int src = (e < beg) ? n : g_col[e];
        float t0 = g_as1[src * 4 + h0] + ad0;  t0 = (t0 > 0.f) ? t0 : 0.2f * t0;
        float t1 = g_as1[src * 4 + h1] + ad1v; t1 = (t1 > 0.f) ? t1 : 0.2f * t1;
        float x0 = __expf(t0), x1 = __expf(t1);
        uint2 p0 = H[(size_t)src * 64 + lane];
        uint2 p1 = H[(size_t)src * 64 + 32 + lane];
        float2 a = __half22float2(*(const __half2*)&p0.x);
        float2 bq = __half22float2(*(const __half2*)&p0.y);
        float2 c = __half22float2(*(const __half2*)&p1.x);
        float2 d = __half22float2(*(const __half2*)&p1.y);
        acc0.x += x0 * a.x;  acc0.y += x0 * a.y;  acc0.z += x0 * bq.x; acc0.w += x0 * bq.y;
        acc1.x += x1 * c.x;  acc1.y += x1 * c.y;  acc1.z += x1 * d.x;  acc1.w += x1 * d.y;
        s0 += x0; s1 += x1;
    }
    float i0 = 1.f / s0, i1 = 1.f / s1;
    int c0 = lane * 4, c1 = 128 + lane * 4;
    float4 o0, o1;
    o0.x = fmaxf(acc0.x * i0 + b1[c0 + 0], 0.f);
    o0.y = fmaxf(acc0.y * i0 + b1[c0 + 1], 0.f);
    o0.z = fmaxf(acc0.z * i0 + b1[c0 + 2], 0.f);
    o0.w = fmaxf(acc0.w * i0 + b1[c0 + 3], 0.f);
    o1.x = fmaxf(acc1.x * i1 + b1[c1 + 0], 0.f);
    o1.y = fmaxf(acc1.y * i1 + b1[c1 + 1], 0.f);
    o1.z = fmaxf(acc1.z * i1 + b1[c1 + 2], 0.f);
    o1.w = fmaxf(acc1.w * i1 + b1[c1 + 3], 0.f);
    float4* O = (float4*)g_hrelu;
    O[(size_t)n * 64 + lane] = o0;
    O[(size_t)n * 64 + 32 + lane] = o1;
}

// layer2: fp32 gather, counted loop.
__global__ void k_agg2(const float* __restrict__ b2, float* __restrict__ out, int N) {
    int gt = blockIdx.x * blockDim.x + threadIdx.x;
    int n = gt >> 5, lane = gt & 31;
    if (n >= N) return;
    float ad = g_ad2[n];
    const float2* H = (const float2*)g_h2;
    float2 acc = make_float2(0.f, 0.f);
    float s = 0.f;
    int beg = g_rowptr[n], end = g_rowptr[n + 1];
    for (int e = beg - 1; e < end; e++) {
        int src = (e < beg) ? n : g_col[e];
        float t = g_as2[src] + ad; t = (t > 0.f) ? t : 0.2f * t;
        float x = __expf(t);
        float2 v = H[(size_t)src * 32 + lane];
        acc.x += x * v.x; acc.y += x * v.y;
        s += x;
    }
    float inv = 1.f / s;
    float2 o;
    o.x = acc.x * inv + b2[lane * 2 + 0];
    o.y = acc.y * inv + b2[lane * 2 + 1];
    ((float2*)out)[(size_t)n * 32 + lane] = o;
}

// ---------------- launch ----------------
extern "C" void kernel_launch(void* const* d_in, const int* in_sizes, int n_in,
                              void* d_out, int out_size) {
    const float* x    = (const float*)d_in[0];
    const int*   ei   = (const int*)d_in[1];
    const float* W1   = (const float*)d_in[2];
    const float* as1w = (const float*)d_in[3];
    const float* ad1w = (const float*)d_in[4];
    const float* b1   = (const float*)d_in[5];
    const float* W2   = (const float*)d_in[6];
    const float* as2w = (const float*)d_in[7];
    const float* ad2w = (const float*)d_in[8];
    const float* b2   = (const float*)d_in[9];

    int N = in_sizes[0] / 128;
    int E = in_sizes[1] / 2;
    const int* srcp = ei;
    const int* dstp = ei + E;

    void *p_h1, *p_hrelu, *p_h2;
    cudaGetSymbolAddress(&p_h1, g_h1);
    cudaGetSymbolAddress(&p_hrelu, g_hrelu);
    cudaGetSymbolAddress(&p_h2, g_h2);

    static cudaStream_t s2 = nullptr;
    static cudaEvent_t ev_fork = nullptr, ev_join = nullptr;
    if (!s2) {
        cudaStreamCreateWithFlags(&s2, cudaStreamNonBlocking);
        cudaEventCreateWithFlags(&ev_fork, cudaEventDisableTiming);
        cudaEventCreateWithFlags(&ev_join, cudaEventDisableTiming);
    }

    // fork: CSR build runs concurrently with layer-1 GEMM
    cudaEventRecord(ev_fork, 0);
    cudaStreamWaitEvent(s2, ev_fork, 0);
    k_zero_deg<<<(N + 255) / 256, 256, 0, s2>>>(N);
    k_hist<<<(E + 255) / 256, 256, 0, s2>>>(dstp, E, N);
    k_scan<<<1, 1024, 0, s2>>>(N);
    k_scatter<<<(E + 255) / 256, 256, 0, s2>>>(srcp, dstp, E, N);
    cudaEventRecord(ev_join, s2);

    // layer 1 linear + attention coefficients (independent of CSR)
    dim3 g1(256 / 64, (N + 127) / 128);
    k_sgemm<<<g1, 256>>>(x, W1, (float*)p_h1, N, 256, 128);
    k_alpha1<<<(N * 32 + 255) / 256, 256>>>(as1w, ad1w, N);

    // join, then aggregation + layer 2
    cudaStreamWaitEvent(0, ev_join, 0);
    k_agg1<<<(N * 32 + 255) / 256, 256>>>(b1, N);

    dim3 g2(64 / 64, (N + 127) / 128);
    k_sgemm<<<g2, 256>>>((const float*)p_hrelu, W2, (float*)p_h2, N, 64, 256);
    k_alpha2<<<(N * 32 + 255) / 256, 256>>>(as2w, ad2w, N);
    k_agg2<<<(N * 32 + 255) / 256, 256>>>(b2, (float*)d_out, N);
}